// round 1
// baseline (speedup 1.0000x reference)
#include <cuda_runtime.h>
#include <cuda_bf16.h>
#include <math.h>

// Problem constants (from reference)
#define N_SEQ   128
#define N_RES   768
#define MSA_DIM 256
#define PAIR_DIM 128
#define N_BINS  15
#define EPS     1e-5f

#define MSA_ELEMS   ((long)N_SEQ * N_RES * MSA_DIM)       // 25,165,824
#define PAIR_ELEMS  ((long)N_RES * N_RES * PAIR_DIM)      // 75,497,472
#define SEQ0_ELEMS  ((long)N_RES * MSA_DIM)               // 196,608

// ---------------------------------------------------------------------------
// Pair kernel: 1 warp per (i,j) pair vector of 128 channels. 8 warps/block.
//   out = pair + LN(pair)*g_pair + b_pair + W[:, idx] + b_cb
// W staged transposed in smem so the per-bin gather is a float4 LDS.
// ---------------------------------------------------------------------------
__global__ __launch_bounds__(256, 8)
void pair_kernel(const float* __restrict__ pair,
                 const float* __restrict__ cb,
                 const float* __restrict__ W,      // [PAIR_DIM, N_BINS]
                 const float* __restrict__ b_cb,   // [PAIR_DIM]
                 const float* __restrict__ g_pair, // [PAIR_DIM]
                 const float* __restrict__ b_pair, // [PAIR_DIM]
                 const float* __restrict__ bins,   // [N_BINS]
                 float* __restrict__ out)
{
    __shared__ float sWt[N_BINS * PAIR_DIM]; // transposed: sWt[k*128 + c]
    __shared__ float sBcb[PAIR_DIM];
    __shared__ float sG[PAIR_DIM];
    __shared__ float sBp[PAIR_DIM];
    __shared__ float sBins[N_BINS];

    const int tid = threadIdx.x;
    for (int t = tid; t < N_BINS * PAIR_DIM; t += blockDim.x) {
        int k = t / PAIR_DIM;
        int c = t - k * PAIR_DIM;
        sWt[t] = W[c * N_BINS + k];
    }
    if (tid < PAIR_DIM) {
        sBcb[tid] = b_cb[tid];
        sG[tid]   = g_pair[tid];
        sBp[tid]  = b_pair[tid];
    }
    if (tid < N_BINS) sBins[tid] = bins[tid];
    __syncthreads();

    const int warp = tid >> 5;
    const int lane = tid & 31;
    const int p = blockIdx.x * 8 + warp;           // pair index, < 768*768
    const int i = p / N_RES;
    const int j = p - i * N_RES;

    // distance -> nearest bin (argmin, first-min on ties like jnp.argmin)
    const float dx = cb[3*i + 0] - cb[3*j + 0];
    const float dy = cb[3*i + 1] - cb[3*j + 1];
    const float dz = cb[3*i + 2] - cb[3*j + 2];
    const float d  = sqrtf(dx*dx + dy*dy + dz*dz);
    int   idx  = 0;
    float best = fabsf(d - sBins[0]);
#pragma unroll
    for (int k = 1; k < N_BINS; k++) {
        float a = fabsf(d - sBins[k]);
        if (a < best) { best = a; idx = k; }
    }

    // load 4 channels per lane
    const float4* xin = (const float4*)(pair + (long)p * PAIR_DIM);
    float4 x = xin[lane];

    // mean over 128
    float s = x.x + x.y + x.z + x.w;
#pragma unroll
    for (int o = 16; o; o >>= 1) s += __shfl_xor_sync(0xffffffffu, s, o);
    const float m = s * (1.0f / 128.0f);

    const float d0 = x.x - m, d1 = x.y - m, d2 = x.z - m, d3 = x.w - m;
    float v = d0*d0 + d1*d1 + d2*d2 + d3*d3;
#pragma unroll
    for (int o = 16; o; o >>= 1) v += __shfl_xor_sync(0xffffffffu, v, o);
    const float r = rsqrtf(v * (1.0f / 128.0f) + EPS);

    const int c = lane * 4;
    const float4 g  = *(const float4*)(sG  + c);
    const float4 bp = *(const float4*)(sBp + c);
    const float4 wv = *(const float4*)(sWt + idx * PAIR_DIM + c);
    const float4 bc = *(const float4*)(sBcb + c);

    float4 o4;
    o4.x = x.x + d0 * r * g.x + bp.x + wv.x + bc.x;
    o4.y = x.y + d1 * r * g.y + bp.y + wv.y + bc.y;
    o4.z = x.z + d2 * r * g.z + bp.z + wv.z + bc.z;
    o4.w = x.w + d3 * r * g.w + bp.w + wv.w + bc.w;

    ((float4*)(out + (long)p * PAIR_DIM))[lane] = o4;
}

// ---------------------------------------------------------------------------
// MSA copy: sequences 1..127 are a straight copy. float4 grid-stride.
// ---------------------------------------------------------------------------
__global__ __launch_bounds__(256)
void msa_copy_kernel(const float4* __restrict__ src, float4* __restrict__ dst,
                     long n4)
{
    long t = (long)blockIdx.x * blockDim.x + threadIdx.x;
    long stride = (long)gridDim.x * blockDim.x;
    for (; t < n4; t += stride) dst[t] = src[t];
}

// ---------------------------------------------------------------------------
// MSA seq-0 LN: 768 rows of 256. One warp per row, 8 values/lane (2x float4).
//   out = x + LN(x)*g_msa + b_msa
// ---------------------------------------------------------------------------
__global__ __launch_bounds__(256, 8)
void msa_ln_kernel(const float* __restrict__ msa,   // seq 0 base
                   const float* __restrict__ g_msa,
                   const float* __restrict__ b_msa,
                   float* __restrict__ out)         // seq 0 of output
{
    const int warp = threadIdx.x >> 5;
    const int lane = threadIdx.x & 31;
    const int row = blockIdx.x * 8 + warp;
    if (row >= N_RES) return;

    const float* x = msa + (long)row * MSA_DIM;
    const int c0 = lane * 8;
    float4 a = *(const float4*)(x + c0);
    float4 b = *(const float4*)(x + c0 + 4);

    float s = a.x + a.y + a.z + a.w + b.x + b.y + b.z + b.w;
#pragma unroll
    for (int o = 16; o; o >>= 1) s += __shfl_xor_sync(0xffffffffu, s, o);
    const float m = s * (1.0f / 256.0f);

    float da0 = a.x - m, da1 = a.y - m, da2 = a.z - m, da3 = a.w - m;
    float db0 = b.x - m, db1 = b.y - m, db2 = b.z - m, db3 = b.w - m;
    float v = da0*da0 + da1*da1 + da2*da2 + da3*da3
            + db0*db0 + db1*db1 + db2*db2 + db3*db3;
#pragma unroll
    for (int o = 16; o; o >>= 1) v += __shfl_xor_sync(0xffffffffu, v, o);
    const float r = rsqrtf(v * (1.0f / 256.0f) + EPS);

    float4 ga = *(const float4*)(g_msa + c0);
    float4 gb = *(const float4*)(g_msa + c0 + 4);
    float4 ba = *(const float4*)(b_msa + c0);
    float4 bb = *(const float4*)(b_msa + c0 + 4);

    float4 oa, ob;
    oa.x = a.x + da0 * r * ga.x + ba.x;
    oa.y = a.y + da1 * r * ga.y + ba.y;
    oa.z = a.z + da2 * r * ga.z + ba.z;
    oa.w = a.w + da3 * r * ga.w + ba.w;
    ob.x = b.x + db0 * r * gb.x + bb.x;
    ob.y = b.y + db1 * r * gb.y + bb.y;
    ob.z = b.z + db2 * r * gb.z + bb.z;
    ob.w = b.w + db3 * r * gb.w + bb.w;

    *(float4*)(out + (long)row * MSA_DIM + c0)     = oa;
    *(float4*)(out + (long)row * MSA_DIM + c0 + 4) = ob;
}

extern "C" void kernel_launch(void* const* d_in, const int* in_sizes, int n_in,
                              void* d_out, int out_size)
{
    // Input order per setup_inputs():
    // 0 msa_rep [128,768,256], 1 pair_rep [768,768,128], 2 prev_struct_cb [768,3],
    // 3 W [128,15], 4 b [128], 5 g_pair [128], 6 b_pair [128],
    // 7 g_msa [256], 8 b_msa [256], 9 bins [15]
    const float* msa    = (const float*)d_in[0];
    const float* pair   = (const float*)d_in[1];
    const float* cb     = (const float*)d_in[2];
    const float* W      = (const float*)d_in[3];
    const float* b_cb   = (const float*)d_in[4];
    const float* g_pair = (const float*)d_in[5];
    const float* b_pair = (const float*)d_in[6];
    const float* g_msa  = (const float*)d_in[7];
    const float* b_msa  = (const float*)d_in[8];
    const float* bins   = (const float*)d_in[9];

    float* out_msa  = (float*)d_out;               // [128,768,256]
    float* out_pair = out_msa + MSA_ELEMS;         // [768,768,128]

    // 1) copy MSA sequences 1..127 (skip seq 0 region)
    {
        long n4 = (MSA_ELEMS - SEQ0_ELEMS) / 4;    // 6,242,304 float4
        int blocks = (int)((n4 + 255) / 256);
        msa_copy_kernel<<<blocks, 256>>>(
            (const float4*)(msa + SEQ0_ELEMS),
            (float4*)(out_msa + SEQ0_ELEMS), n4);
    }

    // 2) seq-0 LN-add (768 rows, 8 rows/block)
    msa_ln_kernel<<<N_RES / 8, 256>>>(msa, g_msa, b_msa, out_msa);

    // 3) pair update: 768*768 pairs, 8 pairs/block
    {
        int blocks = (N_RES * N_RES) / 8;          // 73,728
        pair_kernel<<<blocks, 256>>>(pair, cb, W, b_cb, g_pair, b_pair,
                                     bins, out_pair);
    }
}

// round 2
// speedup vs baseline: 1.0521x; 1.0521x over previous
#include <cuda_runtime.h>
#include <cuda_bf16.h>
#include <math.h>

// Problem constants (from reference)
#define N_SEQ   128
#define N_RES   768
#define MSA_DIM 256
#define PAIR_DIM 128
#define N_BINS  15
#define EPS     1e-5f

#define MSA_ELEMS   ((long)N_SEQ * N_RES * MSA_DIM)       // 25,165,824
#define PAIR_ELEMS  ((long)N_RES * N_RES * PAIR_DIM)      // 75,497,472
#define SEQ0_ELEMS  ((long)N_RES * MSA_DIM)               // 196,608
#define N_PAIRS     (N_RES * N_RES)                       // 589,824

#define PAIR_BLOCKS 1184   // ~8 blocks/SM on 148-SM B200; grid-stride inside

// ---------------------------------------------------------------------------
// Pair kernel (grid-stride, persistent-style):
//   out = pair + LN(pair)*g_pair + (W[:,idx] + b_cb + b_pair)
// Combined table sC[bin][c] = W[c][bin] + b_cb[c] + b_pair[c] staged ONCE per
// block (only 1184 blocks). Each warp processes 2 pairs per iteration with the
// two dependency chains interleaved for MLP=2.
// ---------------------------------------------------------------------------
__global__ __launch_bounds__(256, 8)
void pair_kernel(const float* __restrict__ pair,
                 const float* __restrict__ cb,
                 const float* __restrict__ W,      // [PAIR_DIM, N_BINS]
                 const float* __restrict__ b_cb,   // [PAIR_DIM]
                 const float* __restrict__ g_pair, // [PAIR_DIM]
                 const float* __restrict__ b_pair, // [PAIR_DIM]
                 const float* __restrict__ bins,   // [N_BINS]
                 float* __restrict__ out)
{
    __shared__ float sC[N_BINS * PAIR_DIM];  // W^T + b_cb + b_pair, [k][c]
    __shared__ float sG[PAIR_DIM];
    __shared__ float sBins[N_BINS];

    const int tid = threadIdx.x;
    for (int t = tid; t < N_BINS * PAIR_DIM; t += 256) {
        int k = t >> 7;               // / PAIR_DIM
        int c = t & (PAIR_DIM - 1);
        sC[t] = W[c * N_BINS + k] + b_cb[c] + b_pair[c];
    }
    if (tid < PAIR_DIM) sG[tid] = g_pair[tid];
    if (tid < N_BINS)   sBins[tid] = bins[tid];
    __syncthreads();

    const int warp = tid >> 5;
    const int lane = tid & 31;
    const int gw = blockIdx.x * 8 + warp;          // global warp id
    const long wstride = (long)PAIR_BLOCKS * 8 * 2;

    const int c = lane * 4;
    const float4 g = *(const float4*)(sG + c);

    for (long p0 = (long)gw * 2; p0 < N_PAIRS; p0 += wstride) {
        const long p1 = p0 + 1;

        // ---- bin indices for both pairs ----
        const int i0 = (int)(p0 / N_RES), j0 = (int)(p0 - (long)i0 * N_RES);
        const int i1 = (int)(p1 / N_RES), j1 = (int)(p1 - (long)i1 * N_RES);

        float dx0 = cb[3*i0+0] - cb[3*j0+0];
        float dy0 = cb[3*i0+1] - cb[3*j0+1];
        float dz0 = cb[3*i0+2] - cb[3*j0+2];
        float dx1 = cb[3*i1+0] - cb[3*j1+0];
        float dy1 = cb[3*i1+1] - cb[3*j1+1];
        float dz1 = cb[3*i1+2] - cb[3*j1+2];
        float dd0 = sqrtf(dx0*dx0 + dy0*dy0 + dz0*dz0);
        float dd1 = sqrtf(dx1*dx1 + dy1*dy1 + dz1*dz1);

        int   idx0 = 0, idx1 = 0;
        float best0 = fabsf(dd0 - sBins[0]);
        float best1 = fabsf(dd1 - sBins[0]);
#pragma unroll
        for (int k = 1; k < N_BINS; k++) {
            float bk = sBins[k];
            float a0 = fabsf(dd0 - bk);
            float a1 = fabsf(dd1 - bk);
            if (a0 < best0) { best0 = a0; idx0 = k; }
            if (a1 < best1) { best1 = a1; idx1 = k; }
        }

        // ---- two independent LN chains, interleaved ----
        float4 x0 = ((const float4*)(pair + p0 * PAIR_DIM))[lane];
        float4 x1 = ((const float4*)(pair + p1 * PAIR_DIM))[lane];

        float s0 = x0.x + x0.y + x0.z + x0.w;
        float s1 = x1.x + x1.y + x1.z + x1.w;
#pragma unroll
        for (int o = 16; o; o >>= 1) {
            s0 += __shfl_xor_sync(0xffffffffu, s0, o);
            s1 += __shfl_xor_sync(0xffffffffu, s1, o);
        }
        const float m0 = s0 * (1.0f / 128.0f);
        const float m1 = s1 * (1.0f / 128.0f);

        float a00 = x0.x - m0, a01 = x0.y - m0, a02 = x0.z - m0, a03 = x0.w - m0;
        float a10 = x1.x - m1, a11 = x1.y - m1, a12 = x1.z - m1, a13 = x1.w - m1;
        float v0 = a00*a00 + a01*a01 + a02*a02 + a03*a03;
        float v1 = a10*a10 + a11*a11 + a12*a12 + a13*a13;
#pragma unroll
        for (int o = 16; o; o >>= 1) {
            v0 += __shfl_xor_sync(0xffffffffu, v0, o);
            v1 += __shfl_xor_sync(0xffffffffu, v1, o);
        }
        const float r0 = rsqrtf(v0 * (1.0f / 128.0f) + EPS);
        const float r1 = rsqrtf(v1 * (1.0f / 128.0f) + EPS);

        const float4 c0 = *(const float4*)(sC + idx0 * PAIR_DIM + c);
        const float4 c1 = *(const float4*)(sC + idx1 * PAIR_DIM + c);

        float4 o0, o1;
        o0.x = x0.x + a00 * r0 * g.x + c0.x;
        o0.y = x0.y + a01 * r0 * g.y + c0.y;
        o0.z = x0.z + a02 * r0 * g.z + c0.z;
        o0.w = x0.w + a03 * r0 * g.w + c0.w;
        o1.x = x1.x + a10 * r1 * g.x + c1.x;
        o1.y = x1.y + a11 * r1 * g.y + c1.y;
        o1.z = x1.z + a12 * r1 * g.z + c1.z;
        o1.w = x1.w + a13 * r1 * g.w + c1.w;

        ((float4*)(out + p0 * PAIR_DIM))[lane] = o0;
        ((float4*)(out + p1 * PAIR_DIM))[lane] = o1;
    }
}

// ---------------------------------------------------------------------------
// MSA copy: sequences 1..127 are a straight copy. float4 grid-stride.
// (Already measured at the 6.26 TB/s LTS cap — leave as is.)
// ---------------------------------------------------------------------------
__global__ __launch_bounds__(256)
void msa_copy_kernel(const float4* __restrict__ src, float4* __restrict__ dst,
                     long n4)
{
    long t = (long)blockIdx.x * blockDim.x + threadIdx.x;
    long stride = (long)gridDim.x * blockDim.x;
    for (; t < n4; t += stride) dst[t] = src[t];
}

// ---------------------------------------------------------------------------
// MSA seq-0 LN: 768 rows of 256. One warp per row, 8 values/lane.
//   out = x + LN(x)*g_msa + b_msa
// ---------------------------------------------------------------------------
__global__ __launch_bounds__(256, 8)
void msa_ln_kernel(const float* __restrict__ msa,
                   const float* __restrict__ g_msa,
                   const float* __restrict__ b_msa,
                   float* __restrict__ out)
{
    const int warp = threadIdx.x >> 5;
    const int lane = threadIdx.x & 31;
    const int row = blockIdx.x * 8 + warp;
    if (row >= N_RES) return;

    const float* x = msa + (long)row * MSA_DIM;
    const int c0 = lane * 8;
    float4 a = *(const float4*)(x + c0);
    float4 b = *(const float4*)(x + c0 + 4);

    float s = a.x + a.y + a.z + a.w + b.x + b.y + b.z + b.w;
#pragma unroll
    for (int o = 16; o; o >>= 1) s += __shfl_xor_sync(0xffffffffu, s, o);
    const float m = s * (1.0f / 256.0f);

    float da0 = a.x - m, da1 = a.y - m, da2 = a.z - m, da3 = a.w - m;
    float db0 = b.x - m, db1 = b.y - m, db2 = b.z - m, db3 = b.w - m;
    float v = da0*da0 + da1*da1 + da2*da2 + da3*da3
            + db0*db0 + db1*db1 + db2*db2 + db3*db3;
#pragma unroll
    for (int o = 16; o; o >>= 1) v += __shfl_xor_sync(0xffffffffu, v, o);
    const float r = rsqrtf(v * (1.0f / 256.0f) + EPS);

    float4 ga = *(const float4*)(g_msa + c0);
    float4 gb = *(const float4*)(g_msa + c0 + 4);
    float4 ba = *(const float4*)(b_msa + c0);
    float4 bb = *(const float4*)(b_msa + c0 + 4);

    float4 oa, ob;
    oa.x = a.x + da0 * r * ga.x + ba.x;
    oa.y = a.y + da1 * r * ga.y + ba.y;
    oa.z = a.z + da2 * r * ga.z + ba.z;
    oa.w = a.w + da3 * r * ga.w + ba.w;
    ob.x = b.x + db0 * r * gb.x + bb.x;
    ob.y = b.y + db1 * r * gb.y + bb.y;
    ob.z = b.z + db2 * r * gb.z + bb.z;
    ob.w = b.w + db3 * r * gb.w + bb.w;

    *(float4*)(out + (long)row * MSA_DIM + c0)     = oa;
    *(float4*)(out + (long)row * MSA_DIM + c0 + 4) = ob;
}

extern "C" void kernel_launch(void* const* d_in, const int* in_sizes, int n_in,
                              void* d_out, int out_size)
{
    const float* msa    = (const float*)d_in[0];
    const float* pair   = (const float*)d_in[1];
    const float* cb     = (const float*)d_in[2];
    const float* W      = (const float*)d_in[3];
    const float* b_cb   = (const float*)d_in[4];
    const float* g_pair = (const float*)d_in[5];
    const float* b_pair = (const float*)d_in[6];
    const float* g_msa  = (const float*)d_in[7];
    const float* b_msa  = (const float*)d_in[8];
    const float* bins   = (const float*)d_in[9];

    float* out_msa  = (float*)d_out;               // [128,768,256]
    float* out_pair = out_msa + MSA_ELEMS;         // [768,768,128]

    // 1) pair update (the big one) — grid-stride persistent style
    pair_kernel<<<PAIR_BLOCKS, 256>>>(pair, cb, W, b_cb, g_pair, b_pair,
                                      bins, out_pair);

    // 2) copy MSA sequences 1..127
    {
        long n4 = (MSA_ELEMS - SEQ0_ELEMS) / 4;
        int blocks = (int)((n4 + 255) / 256);
        msa_copy_kernel<<<blocks, 256>>>(
            (const float4*)(msa + SEQ0_ELEMS),
            (float4*)(out_msa + SEQ0_ELEMS), n4);
    }

    // 3) seq-0 LN-add
    msa_ln_kernel<<<N_RES / 8, 256>>>(msa, g_msa, b_msa, out_msa);
}